// round 6
// baseline (speedup 1.0000x reference)
#include <cuda_runtime.h>
#include <cuda_fp16.h>
#include <math.h>

#define NN 50000
#define EE 800000
#define IND 128
#define EDIM 16
#define HH 8
#define HD 64

#define K23_EPB 32                     // 8 warps x 4 edges
#define K23_GRID (EE / K23_EPB)        // 25000
#define PREP_GRID (2 * EE / 256)       // 6250
#define EXP_OFS 30.0f

// ---------------- scratch (device globals: no allocation allowed) ----------------
__device__ __align__(16) float  g_buf[NN * HD];     // fp32 g, for k4 (12.8 MB)
__device__ __align__(16) __half g_half[NN * HD];    // fp16 g, for k23 gathers; row = 128B = 1 line
__device__ __align__(16) float  S_buf[NN * HH];     // 1.6 MB
__device__ __align__(16) float  Gmat_d[HD * IND];
__device__ __align__(16) float  Mmat_d[HH * EDIM];
__device__ __align__(128) float Zpad[HH * 32];      // one head per 128B line
__device__ int   idx_buf[2 * EE];

// ---------------- fused prep: dtype-normalize idx + zero S/Z + fold weights ----------------
__global__ __launch_bounds__(256) void k_prep(const void* __restrict__ p,
                                              const float* __restrict__ W,
                                              const float* __restrict__ W_edge,
                                              const float* __restrict__ W_edge_att,
                                              const float* __restrict__ W_att) {
    __shared__ int s64;
    int tid = threadIdx.x;
    if (tid < 32) {
        unsigned int v = ((const unsigned int*)p)[2 * tid + 1];
        unsigned int ball = __ballot_sync(0xffffffffu, v == 0u);
        if (tid == 0) s64 = (ball == 0xffffffffu) ? 1 : 0;
    }
    __syncthreads();
    int is64 = s64;

    int i = blockIdx.x * 256 + tid;
    if (i < 2 * EE)
        idx_buf[i] = is64 ? (int)((const long long*)p)[i] : ((const int*)p)[i];

    if (tid < 16) {
        int zi = blockIdx.x * 64 + tid * 4;
        if (zi < NN * HH)
            *(float4*)(S_buf + zi) = make_float4(0.f, 0.f, 0.f, 0.f);
    }

    if (blockIdx.x == 0) {
        if (tid < HH * 32) Zpad[tid] = 0.f;
        if (tid < HH * EDIM) {
            int h = tid / EDIM, c = tid % EDIM;
            float s = 0.f;
            #pragma unroll 8
            for (int j = 0; j < 64; j++) s += W_edge_att[h * 64 + j] * W_edge[j * EDIM + c];
            Mmat_d[tid] = s;
        }
        for (int idx = tid; idx < HD * IND; idx += 256) {
            int j = idx / IND, c = idx % IND;
            int h = j / 8, k = j % 8;
            float s = 0.f;
            #pragma unroll
            for (int d = 0; d < 8; d++) s += W_att[k * 8 + d] * W[(h * 8 + d) * IND + c];
            Gmat_d[idx] = s;
        }
    }
}

// ---------------- k1: g = x @ Gmat^T  ([N,128] -> [N,64]), dual fp32+fp16 output ----------------
__global__ __launch_bounds__(256) void k1(const float* __restrict__ x) {
    __shared__ float sx[128][33];
    __shared__ float sg[64][33];
    int tid = threadIdx.x;
    int n0 = blockIdx.x * 128;
    int tr = (tid / 16) * 8;
    int tc = (tid % 16) * 4;
    float acc[8][4];
    #pragma unroll
    for (int r = 0; r < 8; r++)
        #pragma unroll
        for (int c = 0; c < 4; c++) acc[r][c] = 0.f;

    for (int kc = 0; kc < IND; kc += 32) {
        for (int l = tid; l < 128 * 8; l += 256) {
            int r = l / 8, c4 = (l % 8) * 4;
            int gr = n0 + r;
            float4 v = (gr < NN) ? *(const float4*)(x + (size_t)gr * IND + kc + c4)
                                 : make_float4(0.f, 0.f, 0.f, 0.f);
            sx[r][c4] = v.x; sx[r][c4 + 1] = v.y; sx[r][c4 + 2] = v.z; sx[r][c4 + 3] = v.w;
        }
        for (int l = tid; l < 64 * 8; l += 256) {
            int r = l / 8, c4 = (l % 8) * 4;
            float4 v = *(const float4*)(Gmat_d + r * IND + kc + c4);
            sg[r][c4] = v.x; sg[r][c4 + 1] = v.y; sg[r][c4 + 2] = v.z; sg[r][c4 + 3] = v.w;
        }
        __syncthreads();
        #pragma unroll 8
        for (int k = 0; k < 32; k++) {
            float gv[4];
            #pragma unroll
            for (int c = 0; c < 4; c++) gv[c] = sg[tc + c][k];
            #pragma unroll
            for (int r = 0; r < 8; r++) {
                float xv = sx[tr + r][k];
                #pragma unroll
                for (int c = 0; c < 4; c++) acc[r][c] += xv * gv[c];
            }
        }
        __syncthreads();
    }
    #pragma unroll
    for (int r = 0; r < 8; r++) {
        int gr = n0 + tr + r;
        if (gr < NN) {
            *(float4*)(g_buf + (size_t)gr * HD + tc) =
                make_float4(acc[r][0], acc[r][1], acc[r][2], acc[r][3]);
            __half2* hp = (__half2*)(g_half + (size_t)gr * HD + tc);
            hp[0] = __floats2half2_rn(acc[r][0], acc[r][1]);
            hp[1] = __floats2half2_rn(acc[r][2], acc[r][3]);
        }
    }
}

// ---------------- k23: 8-lanes-per-edge, one head per lane ----------------
// warp = 4 edges; lane sub=lane&7 owns head sub (one uint4 of the g_half row).
// Gather: ONE instruction per side per warp, 4 lines each -> 2 line-accesses/edge (floor).
__global__ __launch_bounds__(256) void k23(const float* __restrict__ edge_attr) {
    __shared__ float sMt[EDIM * HH];   // transposed: sMt[c*8+h] (conflict-free lane->head)
    __shared__ float sz[8][HH];
    int tid = threadIdx.x;
    if (tid < EDIM * HH) {
        int c = tid / HH, h = tid % HH;
        sMt[tid] = Mmat_d[h * EDIM + c];
    }
    __syncthreads();

    int lane = tid & 31, wid = tid >> 5;
    int sub = lane & 7;                 // head index
    int e = blockIdx.x * K23_EPB + wid * 4 + (lane >> 3);

    int src = __ldcs(idx_buf + e);
    int dst = __ldcs(idx_buf + EE + e);

    // full att row per lane (8 lanes of an edge dedupe onto the same lines)
    float att[16];
    const float4* ap = (const float4*)(edge_attr + (size_t)e * EDIM);
    #pragma unroll
    for (int q = 0; q < 4; q++) {
        float4 v = __ldcs(ap + q);
        att[q * 4] = v.x; att[q * 4 + 1] = v.y; att[q * 4 + 2] = v.z; att[q * 4 + 3] = v.w;
    }
    float ea = 0.f;
    #pragma unroll
    for (int c = 0; c < 16; c++) ea += att[c] * sMt[c * 8 + sub];

    // one gather per side: lane's head = one uint4
    uint4 ua = ((const uint4*)(g_half + (size_t)src * HD))[sub];
    uint4 ub = ((const uint4*)(g_half + (size_t)dst * HD))[sub];
    float2 a, b;
    float d = 0.f;
    a = __half22float2(*(__half2*)&ua.x); b = __half22float2(*(__half2*)&ub.x); d += a.x*b.x + a.y*b.y;
    a = __half22float2(*(__half2*)&ua.y); b = __half22float2(*(__half2*)&ub.y); d += a.x*b.x + a.y*b.y;
    a = __half22float2(*(__half2*)&ua.z); b = __half22float2(*(__half2*)&ub.z); d += a.x*b.x + a.y*b.y;
    a = __half22float2(*(__half2*)&ua.w); b = __half22float2(*(__half2*)&ub.w); d += a.x*b.x + a.y*b.y;

    float s = d + 8.f * ea;                 // edge_term = ea * D
    s = (s > 0.f) ? s : 0.2f * s;           // leaky_relu(0.2)
    float p = __expf(s - EXP_OFS);

    // pack 4 heads into one lane -> v4 red from lanes sub=0 (heads 0-3) and sub=4 (heads 4-7)
    float t1 = __shfl_xor_sync(0xffffffffu, p, 1);
    float t2 = __shfl_xor_sync(0xffffffffu, p, 2);
    float t3 = __shfl_xor_sync(0xffffffffu, p, 3);
    if ((sub & 3) == 0) {
        float* sp = S_buf + (size_t)dst * 8 + sub;
        asm volatile("red.global.add.v4.f32 [%0], {%1,%2,%3,%4};"
                     :: "l"(sp), "f"(p), "f"(t1), "f"(t2), "f"(t3) : "memory");
    }

    // Z: sum over the 4 edges of this warp (lanes same head, different edge)
    float z = p;
    z += __shfl_xor_sync(0xffffffffu, z, 8);
    z += __shfl_xor_sync(0xffffffffu, z, 16);
    if (lane < 8) sz[wid][lane] = z;
    __syncthreads();
    if (tid < 8) {
        float acc = 0.f;
        #pragma unroll
        for (int w = 0; w < 8; w++) acc += sz[w][tid];
        atomicAdd(&Zpad[tid * 32], acc);
    }
}

// ---------------- k4: cooperative 4-lanes-per-node epilogue ----------------
__global__ __launch_bounds__(256) void k4(const float* __restrict__ W_out, float* __restrict__ out) {
    __shared__ float sw[8 * 68];       // sw[h*68 + k*8 + d]
    __shared__ float sinvZ[8];
    int tid = threadIdx.x;
    for (int i = tid; i < 512; i += 256) {
        int k = i / 64, r = i % 64;
        int h = r / 8, d = r % 8;
        sw[h * 68 + k * 8 + d] = W_out[i];
    }
    if (tid < 8) sinvZ[tid] = 1.0f / Zpad[tid * 32];
    __syncthreads();

    int lane = tid & 31, wid = tid >> 5;
    int j = lane & 3;
    int n = blockIdx.x * 64 + wid * 8 + (lane >> 2);
    int nc = (n < NN) ? n : (NN - 1);
    int h0 = 2 * j, h1 = 2 * j + 1;

    const float4* gp = (const float4*)(g_buf + (size_t)nc * HD) + 4 * j;
    float4 G0 = gp[0], G1 = gp[1], G2 = gp[2], G3 = gp[3];
    float2 S2 = *(const float2*)(S_buf + (size_t)nc * 8 + 2 * j);
    float sv0 = S2.x * sinvZ[h0];
    float sv1 = S2.y * sinvZ[h1];

    float ga[8] = { G0.x*sv0, G0.y*sv0, G0.z*sv0, G0.w*sv0, G1.x*sv0, G1.y*sv0, G1.z*sv0, G1.w*sv0 };
    float gb[8] = { G2.x*sv1, G2.y*sv1, G2.z*sv1, G2.w*sv1, G3.x*sv1, G3.y*sv1, G3.z*sv1, G3.w*sv1 };

    float acc[8];
    #pragma unroll
    for (int k = 0; k < 8; k++) {
        const float* w0 = sw + h0 * 68 + k * 8;
        const float* w1 = sw + h1 * 68 + k * 8;
        float s = 0.f;
        #pragma unroll
        for (int d = 0; d < 8; d++) s += ga[d] * w0[d] + gb[d] * w1[d];
        acc[k] = s;
    }
    #pragma unroll
    for (int o = 1; o <= 2; o <<= 1)
        #pragma unroll
        for (int k = 0; k < 8; k++) acc[k] += __shfl_xor_sync(0xffffffffu, acc[k], o);

    if (n < NN) {
        float2 r;
        r.x = fmaxf(acc[2 * j], 0.f);
        r.y = fmaxf(acc[2 * j + 1], 0.f);
        *(float2*)(out + (size_t)n * 8 + 2 * j) = r;
    }
}

// ---------------- launch ----------------
extern "C" void kernel_launch(void* const* d_in, const int* in_sizes, int n_in,
                              void* d_out, int out_size) {
    const float* x          = (const float*)d_in[0];
    const float* edge_attr  = (const float*)d_in[1];
    const float* W          = (const float*)d_in[2];
    const float* W_edge     = (const float*)d_in[3];
    const float* W_edge_att = (const float*)d_in[4];
    const float* W_att      = (const float*)d_in[5];
    const float* W_out      = (const float*)d_in[6];
    const void*  ei         = d_in[7];
    float* out = (float*)d_out;
    (void)in_sizes; (void)n_in; (void)out_size;

    k_prep<<<PREP_GRID, 256>>>(ei, W, W_edge, W_edge_att, W_att);
    k1<<<(NN + 127) / 128, 256>>>(x);
    k23<<<K23_GRID, 256>>>(edge_attr);
    k4<<<(NN + 63) / 64, 256>>>(W_out, out);
}

// round 7
// speedup vs baseline: 1.2358x; 1.2358x over previous
#include <cuda_runtime.h>
#include <cuda_fp16.h>
#include <math.h>

#define NN 50000
#define EE 800000
#define IND 128
#define EDIM 16
#define HH 8
#define HD 64

#define EDGES_PER_BLK 64               // k23: 8 warps x 8 edges (R5 layout)
#define K23_GRID (EE / EDGES_PER_BLK)  // 12500
#define PREP_EPB 128                   // k_prep: edges per block
#define PREP_GRID (EE / PREP_EPB)      // 6250
#define EXP_OFS 30.0f

// ---------------- scratch (device globals: no allocation allowed) ----------------
__device__ __align__(16) float  g_buf[NN * HD];     // fp32 g, for k4 (12.8 MB)
__device__ __align__(16) __half g_half[NN * HD];    // fp16 g for k23 gathers; row = 128B = 1 line
__device__ __align__(16) float  S_buf[NN * HH];     // 1.6 MB
__device__ __align__(16) float  ea_buf[EE * HH];    // precomputed edge attention (25.6 MB)
__device__ __align__(16) float  Gmat_d[HD * IND];
__device__ __align__(128) float Zpad[HH * 32];      // one head per 128B line
__device__ __align__(16) int2   idx2_buf[EE];       // packed (src,dst)

// ---------------- fused prep: idx normalize+pack, ea projection, zero S/Z, fold G ----------------
__global__ __launch_bounds__(256) void k_prep(const void* __restrict__ p,
                                              const float* __restrict__ edge_attr,
                                              const float* __restrict__ W,
                                              const float* __restrict__ W_edge,
                                              const float* __restrict__ W_edge_att,
                                              const float* __restrict__ W_att) {
    __shared__ float sM[HH * EDIM];    // sM[h*16+c]
    __shared__ int s64;
    int tid = threadIdx.x;
    int b = blockIdx.x;

    // int64-vs-int32 detection (jnp.int64 silently becomes int32 when x64 off):
    // if really int64 (<2^31), every odd 32-bit word is 0; 32 zero high words is conclusive.
    if (tid < 32) {
        unsigned int v = ((const unsigned int*)p)[2 * tid + 1];
        unsigned int ball = __ballot_sync(0xffffffffu, v == 0u);
        if (tid == 0) s64 = (ball == 0xffffffffu) ? 1 : 0;
    }
    // per-block M recompute (tiny): M[h][c] = sum_j W_edge_att[h,j] * W_edge[j,c]
    if (tid < HH * EDIM) {
        int h = tid / EDIM, c = tid % EDIM;
        float s = 0.f;
        #pragma unroll 8
        for (int j = 0; j < 64; j++) s += W_edge_att[h * 64 + j] * W_edge[j * EDIM + c];
        sM[tid] = s;
    }
    __syncthreads();
    int is64 = s64;

    // idx pack: threads 0..127 handle this block's 128 edges
    if (tid < PREP_EPB) {
        int e = b * PREP_EPB + tid;
        int src, dst;
        if (is64) { src = (int)((const long long*)p)[e]; dst = (int)((const long long*)p)[EE + e]; }
        else      { src = ((const int*)p)[e];            dst = ((const int*)p)[EE + e]; }
        idx2_buf[e] = make_int2(src, dst);
    }

    // ea projection: 2 threads per edge (4 heads each), same summation order as before
    {
        int e = b * PREP_EPB + (tid & 127);
        int half = tid >> 7;             // 0: heads 0-3, 1: heads 4-7
        float att[16];
        const float4* ap = (const float4*)(edge_attr + (size_t)e * EDIM);
        #pragma unroll
        for (int q = 0; q < 4; q++) {
            float4 v = __ldcs(ap + q);
            att[q * 4] = v.x; att[q * 4 + 1] = v.y; att[q * 4 + 2] = v.z; att[q * 4 + 3] = v.w;
        }
        float r[4];
        #pragma unroll
        for (int hh = 0; hh < 4; hh++) {
            int h = half * 4 + hh;
            float s = 0.f;
            #pragma unroll
            for (int c = 0; c < 16; c++) s += att[c] * sM[h * 16 + c];
            r[hh] = s;
        }
        *(float4*)(ea_buf + (size_t)e * 8 + half * 4) = make_float4(r[0], r[1], r[2], r[3]);
    }

    // zero S: 400000 floats / 6250 blocks = 64 per block
    if (tid < 16) {
        int zi = b * 64 + tid * 4;
        if (zi < NN * HH)
            *(float4*)(S_buf + zi) = make_float4(0.f, 0.f, 0.f, 0.f);
    }

    if (b == 0) {
        if (tid < HH * 32) Zpad[tid] = 0.f;
        // Gmat[h*8+k][i] = sum_d W_att[k,d] * W[h*8+d, i]
        for (int idx = tid; idx < HD * IND; idx += 256) {
            int j = idx / IND, c = idx % IND;
            int h = j / 8, k = j % 8;
            float s = 0.f;
            #pragma unroll
            for (int d = 0; d < 8; d++) s += W_att[k * 8 + d] * W[(h * 8 + d) * IND + c];
            Gmat_d[idx] = s;
        }
    }
}

// ---------------- k1: g = x @ Gmat^T  ([N,128] -> [N,64]), dual fp32+fp16 output ----------------
__global__ __launch_bounds__(256) void k1(const float* __restrict__ x) {
    __shared__ float sx[128][33];
    __shared__ float sg[64][33];
    int tid = threadIdx.x;
    int n0 = blockIdx.x * 128;
    int tr = (tid / 16) * 8;
    int tc = (tid % 16) * 4;
    float acc[8][4];
    #pragma unroll
    for (int r = 0; r < 8; r++)
        #pragma unroll
        for (int c = 0; c < 4; c++) acc[r][c] = 0.f;

    for (int kc = 0; kc < IND; kc += 32) {
        for (int l = tid; l < 128 * 8; l += 256) {
            int r = l / 8, c4 = (l % 8) * 4;
            int gr = n0 + r;
            float4 v = (gr < NN) ? *(const float4*)(x + (size_t)gr * IND + kc + c4)
                                 : make_float4(0.f, 0.f, 0.f, 0.f);
            sx[r][c4] = v.x; sx[r][c4 + 1] = v.y; sx[r][c4 + 2] = v.z; sx[r][c4 + 3] = v.w;
        }
        for (int l = tid; l < 64 * 8; l += 256) {
            int r = l / 8, c4 = (l % 8) * 4;
            float4 v = *(const float4*)(Gmat_d + r * IND + kc + c4);
            sg[r][c4] = v.x; sg[r][c4 + 1] = v.y; sg[r][c4 + 2] = v.z; sg[r][c4 + 3] = v.w;
        }
        __syncthreads();
        #pragma unroll 8
        for (int k = 0; k < 32; k++) {
            float gv[4];
            #pragma unroll
            for (int c = 0; c < 4; c++) gv[c] = sg[tc + c][k];
            #pragma unroll
            for (int r = 0; r < 8; r++) {
                float xv = sx[tr + r][k];
                #pragma unroll
                for (int c = 0; c < 4; c++) acc[r][c] += xv * gv[c];
            }
        }
        __syncthreads();
    }
    #pragma unroll
    for (int r = 0; r < 8; r++) {
        int gr = n0 + tr + r;
        if (gr < NN) {
            *(float4*)(g_buf + (size_t)gr * HD + tc) =
                make_float4(acc[r][0], acc[r][1], acc[r][2], acc[r][3]);
            __half2* hp = (__half2*)(g_half + (size_t)gr * HD + tc);
            hp[0] = __floats2half2_rn(acc[r][0], acc[r][1]);
            hp[1] = __floats2half2_rn(acc[r][2], acc[r][3]);
        }
    }
}

// ---------------- k23: 4-lanes-per-edge (R5 layout), slim instruction stream ----------------
// warp = 8 edges; lane j=lane&3 owns heads {2j, 2j+1}. ea precomputed; idx packed.
__global__ __launch_bounds__(256) void k23() {
    __shared__ float sz[8][HH];
    int tid = threadIdx.x;
    int lane = tid & 31, wid = tid >> 5;
    int j = lane & 3;
    int e = blockIdx.x * EDGES_PER_BLK + wid * 8 + (lane >> 2);

    int2 sd = __ldcs(idx2_buf + e);                      // 4 lanes dedupe on same addr
    float2 ea2 = __ldcs((const float2*)(ea_buf + (size_t)e * 8 + 2 * j));  // coalesced 256B/warp

    const uint4* gs = (const uint4*)(g_half + (size_t)sd.x * HD);
    const uint4* gd = (const uint4*)(g_half + (size_t)sd.y * HD);
    uint4 ua0 = gs[2 * j], ua1 = gs[2 * j + 1];
    uint4 ub0 = gd[2 * j], ub1 = gd[2 * j + 1];

    float2 a, b;
    float d0 = 0.f, d1 = 0.f;
    a = __half22float2(*(__half2*)&ua0.x); b = __half22float2(*(__half2*)&ub0.x); d0 += a.x*b.x + a.y*b.y;
    a = __half22float2(*(__half2*)&ua0.y); b = __half22float2(*(__half2*)&ub0.y); d0 += a.x*b.x + a.y*b.y;
    a = __half22float2(*(__half2*)&ua0.z); b = __half22float2(*(__half2*)&ub0.z); d0 += a.x*b.x + a.y*b.y;
    a = __half22float2(*(__half2*)&ua0.w); b = __half22float2(*(__half2*)&ub0.w); d0 += a.x*b.x + a.y*b.y;
    a = __half22float2(*(__half2*)&ua1.x); b = __half22float2(*(__half2*)&ub1.x); d1 += a.x*b.x + a.y*b.y;
    a = __half22float2(*(__half2*)&ua1.y); b = __half22float2(*(__half2*)&ub1.y); d1 += a.x*b.x + a.y*b.y;
    a = __half22float2(*(__half2*)&ua1.z); b = __half22float2(*(__half2*)&ub1.z); d1 += a.x*b.x + a.y*b.y;
    a = __half22float2(*(__half2*)&ua1.w); b = __half22float2(*(__half2*)&ub1.w); d1 += a.x*b.x + a.y*b.y;

    float s0 = d0 + 8.f * ea2.x; s0 = (s0 > 0.f) ? s0 : 0.2f * s0;
    float s1 = d1 + 8.f * ea2.y; s1 = (s1 > 0.f) ? s1 : 0.2f * s1;
    float p0 = __expf(s0 - EXP_OFS);
    float p1 = __expf(s1 - EXP_OFS);

    // pair lanes (j, j^1) -> one v4 red per pair (heads 4*(j/2)..+3)
    float q0 = __shfl_xor_sync(0xffffffffu, p0, 1);
    float q1 = __shfl_xor_sync(0xffffffffu, p1, 1);
    if ((j & 1) == 0) {
        float* sp = S_buf + (size_t)sd.y * 8 + j * 2;
        asm volatile("red.global.add.v4.f32 [%0], {%1,%2,%3,%4};"
                     :: "l"(sp), "f"(p0), "f"(p1), "f"(q0), "f"(q1) : "memory");
    }

    // Z partials across the warp's 8 edges
    #pragma unroll
    for (int o = 4; o <= 16; o <<= 1) {
        p0 += __shfl_xor_sync(0xffffffffu, p0, o);
        p1 += __shfl_xor_sync(0xffffffffu, p1, o);
    }
    if (lane < 4) {
        sz[wid][2 * lane]     = p0;
        sz[wid][2 * lane + 1] = p1;
    }
    __syncthreads();
    if (tid < 8) {
        float s = 0.f;
        #pragma unroll
        for (int w = 0; w < 8; w++) s += sz[w][tid];
        atomicAdd(&Zpad[tid * 32], s);
    }
}

// ---------------- k4: cooperative 4-lanes-per-node epilogue ----------------
__global__ __launch_bounds__(256) void k4(const float* __restrict__ W_out, float* __restrict__ out) {
    __shared__ float sw[8 * 68];       // sw[h*68 + k*8 + d]
    __shared__ float sinvZ[8];
    int tid = threadIdx.x;
    for (int i = tid; i < 512; i += 256) {
        int k = i / 64, r = i % 64;
        int h = r / 8, d = r % 8;
        sw[h * 68 + k * 8 + d] = W_out[i];
    }
    if (tid < 8) sinvZ[tid] = 1.0f / Zpad[tid * 32];
    __syncthreads();

    int lane = tid & 31, wid = tid >> 5;
    int j = lane & 3;
    int n = blockIdx.x * 64 + wid * 8 + (lane >> 2);
    int nc = (n < NN) ? n : (NN - 1);
    int h0 = 2 * j, h1 = 2 * j + 1;

    const float4* gp = (const float4*)(g_buf + (size_t)nc * HD) + 4 * j;
    float4 G0 = gp[0], G1 = gp[1], G2 = gp[2], G3 = gp[3];
    float2 S2 = *(const float2*)(S_buf + (size_t)nc * 8 + 2 * j);
    float sv0 = S2.x * sinvZ[h0];
    float sv1 = S2.y * sinvZ[h1];

    float ga[8] = { G0.x*sv0, G0.y*sv0, G0.z*sv0, G0.w*sv0, G1.x*sv0, G1.y*sv0, G1.z*sv0, G1.w*sv0 };
    float gb[8] = { G2.x*sv1, G2.y*sv1, G2.z*sv1, G2.w*sv1, G3.x*sv1, G3.y*sv1, G3.z*sv1, G3.w*sv1 };

    float acc[8];
    #pragma unroll
    for (int k = 0; k < 8; k++) {
        const float* w0 = sw + h0 * 68 + k * 8;
        const float* w1 = sw + h1 * 68 + k * 8;
        float s = 0.f;
        #pragma unroll
        for (int d = 0; d < 8; d++) s += ga[d] * w0[d] + gb[d] * w1[d];
        acc[k] = s;
    }
    #pragma unroll
    for (int o = 1; o <= 2; o <<= 1)
        #pragma unroll
        for (int k = 0; k < 8; k++) acc[k] += __shfl_xor_sync(0xffffffffu, acc[k], o);

    if (n < NN) {
        float2 r;
        r.x = fmaxf(acc[2 * j], 0.f);
        r.y = fmaxf(acc[2 * j + 1], 0.f);
        *(float2*)(out + (size_t)n * 8 + 2 * j) = r;
    }
}

// ---------------- launch ----------------
extern "C" void kernel_launch(void* const* d_in, const int* in_sizes, int n_in,
                              void* d_out, int out_size) {
    const float* x          = (const float*)d_in[0];
    const float* edge_attr  = (const float*)d_in[1];
    const float* W          = (const float*)d_in[2];
    const float* W_edge     = (const float*)d_in[3];
    const float* W_edge_att = (const float*)d_in[4];
    const float* W_att      = (const float*)d_in[5];
    const float* W_out      = (const float*)d_in[6];
    const void*  ei         = d_in[7];
    float* out = (float*)d_out;
    (void)in_sizes; (void)n_in; (void)out_size;

    k_prep<<<PREP_GRID, 256>>>(ei, edge_attr, W, W_edge, W_edge_att, W_att);
    k1<<<(NN + 127) / 128, 256>>>(x);
    k23<<<K23_GRID, 256>>>();
    k4<<<(NN + 63) / 64, 256>>>(W_out, out);
}

// round 8
// speedup vs baseline: 1.6726x; 1.3535x over previous
#include <cuda_runtime.h>
#include <cuda_fp16.h>
#include <math.h>

#define NN 50000
#define EE 800000
#define IND 128
#define EDIM 16
#define HH 8
#define HD 64

#define K23_EPB 128                    // 8 warps x 16 edges (2 per lane-group)
#define K23_GRID (EE / K23_EPB)        // 6250
#define PREP_GRID 6250
#define EXP_OFS 30.0f

// ---------------- scratch (device globals: no allocation allowed) ----------------
__device__ __align__(16) float  g_buf[NN * HD];     // fp32 g, for k4 (12.8 MB)
__device__ __align__(16) __half g_half[NN * HD];    // fp16 g for k23 gathers; row = 128B = 1 line
__device__ __align__(16) float  S_buf[NN * HH];     // 1.6 MB
__device__ __align__(16) float  Gmat_d[HD * IND];
__device__ __align__(16) float  Mmat_d[HH * EDIM];
__device__ __align__(128) float Zpad[HH * 32];      // one head per 128B line
__device__ __align__(16) int2   idx2_buf[EE];       // packed (src,dst)

__device__ __forceinline__ float hdot8(uint4 ua, uint4 ub) {
    float2 a, b; float d = 0.f;
    a = __half22float2(*(__half2*)&ua.x); b = __half22float2(*(__half2*)&ub.x); d += a.x*b.x + a.y*b.y;
    a = __half22float2(*(__half2*)&ua.y); b = __half22float2(*(__half2*)&ub.y); d += a.x*b.x + a.y*b.y;
    a = __half22float2(*(__half2*)&ua.z); b = __half22float2(*(__half2*)&ub.z); d += a.x*b.x + a.y*b.y;
    a = __half22float2(*(__half2*)&ua.w); b = __half22float2(*(__half2*)&ub.w); d += a.x*b.x + a.y*b.y;
    return d;
}

// ---------------- fused prep: idx normalize+pack, zero S/Z, fold weights ----------------
__global__ __launch_bounds__(256) void k_prep(const void* __restrict__ p,
                                              const float* __restrict__ W,
                                              const float* __restrict__ W_edge,
                                              const float* __restrict__ W_edge_att,
                                              const float* __restrict__ W_att) {
    __shared__ int s64;
    int tid = threadIdx.x;
    int b = blockIdx.x;

    // int64-vs-int32 detection (jnp.int64 silently becomes int32 when x64 off):
    // true int64 (<2^31) => every odd 32-bit word is 0; 32 zero high words is conclusive.
    if (tid < 32) {
        unsigned int v = ((const unsigned int*)p)[2 * tid + 1];
        unsigned int ball = __ballot_sync(0xffffffffu, v == 0u);
        if (tid == 0) s64 = (ball == 0xffffffffu) ? 1 : 0;
    }
    __syncthreads();
    int is64 = s64;

    // pack (src,dst): 128 edges per block
    if (tid < 128) {
        int e = b * 128 + tid;
        int src, dst;
        if (is64) { src = (int)((const long long*)p)[e]; dst = (int)((const long long*)p)[EE + e]; }
        else      { src = ((const int*)p)[e];            dst = ((const int*)p)[EE + e]; }
        idx2_buf[e] = make_int2(src, dst);
    }

    // zero S: 400000 floats / 6250 blocks = 64 per block
    if (tid < 16) {
        int zi = b * 64 + tid * 4;
        *(float4*)(S_buf + zi) = make_float4(0.f, 0.f, 0.f, 0.f);
    }

    if (b == 0) {
        if (tid < HH * 32) Zpad[tid] = 0.f;
        // Mmat[h][c] = sum_j W_edge_att[h,j] * W_edge[j,c]
        if (tid < HH * EDIM) {
            int h = tid / EDIM, c = tid % EDIM;
            float s = 0.f;
            #pragma unroll 8
            for (int j = 0; j < 64; j++) s += W_edge_att[h * 64 + j] * W_edge[j * EDIM + c];
            Mmat_d[tid] = s;
        }
        // Gmat[h*8+k][i] = sum_d W_att[k,d] * W[h*8+d, i]
        for (int idx = tid; idx < HD * IND; idx += 256) {
            int j = idx / IND, c = idx % IND;
            int h = j / 8, k = j % 8;
            float s = 0.f;
            #pragma unroll
            for (int d = 0; d < 8; d++) s += W_att[k * 8 + d] * W[(h * 8 + d) * IND + c];
            Gmat_d[idx] = s;
        }
    }
}

// ---------------- k1: g = x @ Gmat^T  ([N,128] -> [N,64]), dual fp32+fp16 output ----------------
__global__ __launch_bounds__(256) void k1(const float* __restrict__ x) {
    __shared__ float sx[128][33];
    __shared__ float sg[64][33];
    int tid = threadIdx.x;
    int n0 = blockIdx.x * 128;
    int tr = (tid / 16) * 8;
    int tc = (tid % 16) * 4;
    float acc[8][4];
    #pragma unroll
    for (int r = 0; r < 8; r++)
        #pragma unroll
        for (int c = 0; c < 4; c++) acc[r][c] = 0.f;

    for (int kc = 0; kc < IND; kc += 32) {
        for (int l = tid; l < 128 * 8; l += 256) {
            int r = l / 8, c4 = (l % 8) * 4;
            int gr = n0 + r;
            float4 v = (gr < NN) ? *(const float4*)(x + (size_t)gr * IND + kc + c4)
                                 : make_float4(0.f, 0.f, 0.f, 0.f);
            sx[r][c4] = v.x; sx[r][c4 + 1] = v.y; sx[r][c4 + 2] = v.z; sx[r][c4 + 3] = v.w;
        }
        for (int l = tid; l < 64 * 8; l += 256) {
            int r = l / 8, c4 = (l % 8) * 4;
            float4 v = *(const float4*)(Gmat_d + r * IND + kc + c4);
            sg[r][c4] = v.x; sg[r][c4 + 1] = v.y; sg[r][c4 + 2] = v.z; sg[r][c4 + 3] = v.w;
        }
        __syncthreads();
        #pragma unroll 8
        for (int k = 0; k < 32; k++) {
            float gv[4];
            #pragma unroll
            for (int c = 0; c < 4; c++) gv[c] = sg[tc + c][k];
            #pragma unroll
            for (int r = 0; r < 8; r++) {
                float xv = sx[tr + r][k];
                #pragma unroll
                for (int c = 0; c < 4; c++) acc[r][c] += xv * gv[c];
            }
        }
        __syncthreads();
    }
    #pragma unroll
    for (int r = 0; r < 8; r++) {
        int gr = n0 + tr + r;
        if (gr < NN) {
            *(float4*)(g_buf + (size_t)gr * HD + tc) =
                make_float4(acc[r][0], acc[r][1], acc[r][2], acc[r][3]);
            __half2* hp = (__half2*)(g_half + (size_t)gr * HD + tc);
            hp[0] = __floats2half2_rn(acc[r][0], acc[r][1]);
            hp[1] = __floats2half2_rn(acc[r][2], acc[r][3]);
        }
    }
}

// ---------------- k23: R5 layout, 2 edges per lane-group (doubled MLP) ----------------
// warp = 16 edges; lane j=lane&3 owns heads {2j,2j+1} of both edges.
__global__ __launch_bounds__(256) void k23(const float* __restrict__ edge_attr) {
    __shared__ float sMt[EDIM * HH];   // sMt[c*8+h]
    __shared__ float sz[8][HH];
    int tid = threadIdx.x;
    if (tid < EDIM * HH) {
        int c = tid / HH, h = tid % HH;
        sMt[tid] = Mmat_d[h * EDIM + c];
    }
    __syncthreads();

    int lane = tid & 31, wid = tid >> 5;
    int j = lane & 3;
    int h0 = 2 * j, h1 = 2 * j + 1;
    int e0 = blockIdx.x * K23_EPB + wid * 16 + (lane >> 2);
    int e1 = e0 + 8;

    // front-batch: idx pairs, att rows, then gathers (dependent only on idx)
    int2 sd0 = __ldcs(idx2_buf + e0);
    int2 sd1 = __ldcs(idx2_buf + e1);

    const float4* ap0 = (const float4*)(edge_attr + (size_t)e0 * EDIM);
    const float4* ap1 = (const float4*)(edge_attr + (size_t)e1 * EDIM);
    float4 av00 = __ldcs(ap0 + 0), av01 = __ldcs(ap0 + 1), av02 = __ldcs(ap0 + 2), av03 = __ldcs(ap0 + 3);
    float4 av10 = __ldcs(ap1 + 0), av11 = __ldcs(ap1 + 1), av12 = __ldcs(ap1 + 2), av13 = __ldcs(ap1 + 3);

    const uint4* gs0 = (const uint4*)(g_half + (size_t)sd0.x * HD);
    const uint4* gd0 = (const uint4*)(g_half + (size_t)sd0.y * HD);
    const uint4* gs1 = (const uint4*)(g_half + (size_t)sd1.x * HD);
    const uint4* gd1 = (const uint4*)(g_half + (size_t)sd1.y * HD);
    uint4 ua00 = gs0[h0], ua01 = gs0[h1], ub00 = gd0[h0], ub01 = gd0[h1];
    uint4 ua10 = gs1[h0], ua11 = gs1[h1], ub10 = gd1[h0], ub11 = gd1[h1];

    // ea projections (consume att while gathers are in flight)
    float ea00, ea01, ea10, ea11;
    {
        const float* m0 = sMt + h0;  // stride 8
        const float* m1 = sMt + h1;
        ea00 = av00.x*m0[0] + av00.y*m0[8]  + av00.z*m0[16] + av00.w*m0[24]
             + av01.x*m0[32] + av01.y*m0[40] + av01.z*m0[48] + av01.w*m0[56]
             + av02.x*m0[64] + av02.y*m0[72] + av02.z*m0[80] + av02.w*m0[88]
             + av03.x*m0[96] + av03.y*m0[104] + av03.z*m0[112] + av03.w*m0[120];
        ea01 = av00.x*m1[0] + av00.y*m1[8]  + av00.z*m1[16] + av00.w*m1[24]
             + av01.x*m1[32] + av01.y*m1[40] + av01.z*m1[48] + av01.w*m1[56]
             + av02.x*m1[64] + av02.y*m1[72] + av02.z*m1[80] + av02.w*m1[88]
             + av03.x*m1[96] + av03.y*m1[104] + av03.z*m1[112] + av03.w*m1[120];
        ea10 = av10.x*m0[0] + av10.y*m0[8]  + av10.z*m0[16] + av10.w*m0[24]
             + av11.x*m0[32] + av11.y*m0[40] + av11.z*m0[48] + av11.w*m0[56]
             + av12.x*m0[64] + av12.y*m0[72] + av12.z*m0[80] + av12.w*m0[88]
             + av13.x*m0[96] + av13.y*m0[104] + av13.z*m0[112] + av13.w*m0[120];
        ea11 = av10.x*m1[0] + av10.y*m1[8]  + av10.z*m1[16] + av10.w*m1[24]
             + av11.x*m1[32] + av11.y*m1[40] + av11.z*m1[48] + av11.w*m1[56]
             + av12.x*m1[64] + av12.y*m1[72] + av12.z*m1[80] + av12.w*m1[88]
             + av13.x*m1[96] + av13.y*m1[104] + av13.z*m1[112] + av13.w*m1[120];
    }

    float d00 = hdot8(ua00, ub00);
    float d01 = hdot8(ua01, ub01);
    float d10 = hdot8(ua10, ub10);
    float d11 = hdot8(ua11, ub11);

    float s00 = d00 + 8.f * ea00; s00 = (s00 > 0.f) ? s00 : 0.2f * s00;
    float s01 = d01 + 8.f * ea01; s01 = (s01 > 0.f) ? s01 : 0.2f * s01;
    float s10 = d10 + 8.f * ea10; s10 = (s10 > 0.f) ? s10 : 0.2f * s10;
    float s11 = d11 + 8.f * ea11; s11 = (s11 > 0.f) ? s11 : 0.2f * s11;
    float p00 = __expf(s00 - EXP_OFS), p01 = __expf(s01 - EXP_OFS);
    float p10 = __expf(s10 - EXP_OFS), p11 = __expf(s11 - EXP_OFS);

    // scatter: pair lanes (j, j^1) -> one v4 red per pair per edge
    float q00 = __shfl_xor_sync(0xffffffffu, p00, 1);
    float q01 = __shfl_xor_sync(0xffffffffu, p01, 1);
    float q10 = __shfl_xor_sync(0xffffffffu, p10, 1);
    float q11 = __shfl_xor_sync(0xffffffffu, p11, 1);
    if ((j & 1) == 0) {
        float* sp0 = S_buf + (size_t)sd0.y * 8 + j * 2;
        asm volatile("red.global.add.v4.f32 [%0], {%1,%2,%3,%4};"
                     :: "l"(sp0), "f"(p00), "f"(p01), "f"(q00), "f"(q01) : "memory");
        float* sp1 = S_buf + (size_t)sd1.y * 8 + j * 2;
        asm volatile("red.global.add.v4.f32 [%0], {%1,%2,%3,%4};"
                     :: "l"(sp1), "f"(p10), "f"(p11), "f"(q10), "f"(q11) : "memory");
    }

    // Z partials: per-head sums over the warp's 16 edges
    float z0 = p00 + p10;
    float z1 = p01 + p11;
    #pragma unroll
    for (int o = 4; o <= 16; o <<= 1) {
        z0 += __shfl_xor_sync(0xffffffffu, z0, o);
        z1 += __shfl_xor_sync(0xffffffffu, z1, o);
    }
    if (lane < 4) {
        sz[wid][2 * lane]     = z0;
        sz[wid][2 * lane + 1] = z1;
    }
    __syncthreads();
    if (tid < 8) {
        float s = 0.f;
        #pragma unroll
        for (int w = 0; w < 8; w++) s += sz[w][tid];
        atomicAdd(&Zpad[tid * 32], s);
    }
}

// ---------------- k4: cooperative 4-lanes-per-node epilogue ----------------
__global__ __launch_bounds__(256) void k4(const float* __restrict__ W_out, float* __restrict__ out) {
    __shared__ float sw[8 * 68];       // sw[h*68 + k*8 + d]
    __shared__ float sinvZ[8];
    int tid = threadIdx.x;
    for (int i = tid; i < 512; i += 256) {
        int k = i / 64, r = i % 64;
        int h = r / 8, d = r % 8;
        sw[h * 68 + k * 8 + d] = W_out[i];
    }
    if (tid < 8) sinvZ[tid] = 1.0f / Zpad[tid * 32];
    __syncthreads();

    int lane = tid & 31, wid = tid >> 5;
    int j = lane & 3;
    int n = blockIdx.x * 64 + wid * 8 + (lane >> 2);
    int nc = (n < NN) ? n : (NN - 1);
    int h0 = 2 * j, h1 = 2 * j + 1;

    const float4* gp = (const float4*)(g_buf + (size_t)nc * HD) + 4 * j;
    float4 G0 = gp[0], G1 = gp[1], G2 = gp[2], G3 = gp[3];
    float2 S2 = *(const float2*)(S_buf + (size_t)nc * 8 + 2 * j);
    float sv0 = S2.x * sinvZ[h0];
    float sv1 = S2.y * sinvZ[h1];

    float ga[8] = { G0.x*sv0, G0.y*sv0, G0.z*sv0, G0.w*sv0, G1.x*sv0, G1.y*sv0, G1.z*sv0, G1.w*sv0 };
    float gb[8] = { G2.x*sv1, G2.y*sv1, G2.z*sv1, G2.w*sv1, G3.x*sv1, G3.y*sv1, G3.z*sv1, G3.w*sv1 };

    float acc[8];
    #pragma unroll
    for (int k = 0; k < 8; k++) {
        const float* w0 = sw + h0 * 68 + k * 8;
        const float* w1 = sw + h1 * 68 + k * 8;
        float s = 0.f;
        #pragma unroll
        for (int d = 0; d < 8; d++) s += ga[d] * w0[d] + gb[d] * w1[d];
        acc[k] = s;
    }
    #pragma unroll
    for (int o = 1; o <= 2; o <<= 1)
        #pragma unroll
        for (int k = 0; k < 8; k++) acc[k] += __shfl_xor_sync(0xffffffffu, acc[k], o);

    if (n < NN) {
        float2 r;
        r.x = fmaxf(acc[2 * j], 0.f);
        r.y = fmaxf(acc[2 * j + 1], 0.f);
        *(float2*)(out + (size_t)n * 8 + 2 * j) = r;
    }
}

// ---------------- launch ----------------
extern "C" void kernel_launch(void* const* d_in, const int* in_sizes, int n_in,
                              void* d_out, int out_size) {
    const float* x          = (const float*)d_in[0];
    const float* edge_attr  = (const float*)d_in[1];
    const float* W          = (const float*)d_in[2];
    const float* W_edge     = (const float*)d_in[3];
    const float* W_edge_att = (const float*)d_in[4];
    const float* W_att      = (const float*)d_in[5];
    const float* W_out      = (const float*)d_in[6];
    const void*  ei         = d_in[7];
    float* out = (float*)d_out;
    (void)in_sizes; (void)n_in; (void)out_size;

    k_prep<<<PREP_GRID, 256>>>(ei, W, W_edge, W_edge_att, W_att);
    k1<<<(NN + 127) / 128, 256>>>(x);
    k23<<<K23_GRID, 256>>>(edge_attr);
    k4<<<(NN + 63) / 64, 256>>>(W_out, out);
}

// round 9
// speedup vs baseline: 1.6838x; 1.0067x over previous
#include <cuda_runtime.h>
#include <cuda_fp16.h>
#include <math.h>

#define NN 50000
#define EE 800000
#define IND 128
#define EDIM 16
#define HH 8
#define HD 64

#define K23_EPB 128                    // 8 warps x 16 edges (2 per lane-group)
#define K23_GRID (EE / K23_EPB)        // 6250
#define PREP_GRID 6250
#define EXP_OFS 30.0f

// ---------------- scratch (device globals: no allocation allowed) ----------------
__device__ __align__(16) float  g_buf[NN * HD];     // fp32 g, for k4 (12.8 MB)
__device__ __align__(16) __half g_half[NN * HD];    // fp16 g for k23 gathers; row = 128B = 1 line
__device__ __align__(16) float  S_buf[NN * HH];     // 1.6 MB
__device__ __align__(16) float  Gmat_d[HD * IND];
__device__ __align__(16) float  Mmat_d[HH * EDIM];
__device__ __align__(128) float Zpad[HH * 32];      // one head per 128B line
__device__ __align__(16) int2   idx2_buf[EE];       // packed (src,dst)

__device__ __forceinline__ float hdot8(uint4 ua, uint4 ub) {
    float2 a, b; float d = 0.f;
    a = __half22float2(*(__half2*)&ua.x); b = __half22float2(*(__half2*)&ub.x); d += a.x*b.x + a.y*b.y;
    a = __half22float2(*(__half2*)&ua.y); b = __half22float2(*(__half2*)&ub.y); d += a.x*b.x + a.y*b.y;
    a = __half22float2(*(__half2*)&ua.z); b = __half22float2(*(__half2*)&ub.z); d += a.x*b.x + a.y*b.y;
    a = __half22float2(*(__half2*)&ua.w); b = __half22float2(*(__half2*)&ub.w); d += a.x*b.x + a.y*b.y;
    return d;
}

// ---------------- fused prep: idx normalize+pack, zero S/Z, fold weights ----------------
__global__ __launch_bounds__(256) void k_prep(const void* __restrict__ p,
                                              const float* __restrict__ W,
                                              const float* __restrict__ W_edge,
                                              const float* __restrict__ W_edge_att,
                                              const float* __restrict__ W_att) {
    __shared__ int s64;
    int tid = threadIdx.x;
    int b = blockIdx.x;

    // int64-vs-int32 detection (jnp.int64 silently becomes int32 when x64 off):
    // true int64 (<2^31) => every odd 32-bit word is 0; 32 zero high words is conclusive.
    if (tid < 32) {
        unsigned int v = ((const unsigned int*)p)[2 * tid + 1];
        unsigned int ball = __ballot_sync(0xffffffffu, v == 0u);
        if (tid == 0) s64 = (ball == 0xffffffffu) ? 1 : 0;
    }
    __syncthreads();
    int is64 = s64;

    // pack (src,dst): 128 edges per block
    if (tid < 128) {
        int e = b * 128 + tid;
        int src, dst;
        if (is64) { src = (int)((const long long*)p)[e]; dst = (int)((const long long*)p)[EE + e]; }
        else      { src = ((const int*)p)[e];            dst = ((const int*)p)[EE + e]; }
        idx2_buf[e] = make_int2(src, dst);
    }

    // zero S: 400000 floats / 6250 blocks = 64 per block
    if (tid < 16) {
        int zi = b * 64 + tid * 4;
        *(float4*)(S_buf + zi) = make_float4(0.f, 0.f, 0.f, 0.f);
    }

    if (b == 0) {
        if (tid < HH * 32) Zpad[tid] = 0.f;
        // Mmat[h][c] = sum_j W_edge_att[h,j] * W_edge[j,c]
        if (tid < HH * EDIM) {
            int h = tid / EDIM, c = tid % EDIM;
            float s = 0.f;
            #pragma unroll 8
            for (int j = 0; j < 64; j++) s += W_edge_att[h * 64 + j] * W_edge[j * EDIM + c];
            Mmat_d[tid] = s;
        }
        // Gmat[h*8+k][i] = sum_d W_att[k,d] * W[h*8+d, i]
        for (int idx = tid; idx < HD * IND; idx += 256) {
            int j = idx / IND, c = idx % IND;
            int h = j / 8, k = j % 8;
            float s = 0.f;
            #pragma unroll
            for (int d = 0; d < 8; d++) s += W_att[k * 8 + d] * W[(h * 8 + d) * IND + c];
            Gmat_d[idx] = s;
        }
    }
}

// ---------------- k1: g = x @ Gmat^T  ([N,128] -> [N,64]), dual fp32+fp16 output ----------------
__global__ __launch_bounds__(256) void k1(const float* __restrict__ x) {
    __shared__ float sx[128][33];
    __shared__ float sg[64][33];
    int tid = threadIdx.x;
    int n0 = blockIdx.x * 128;
    int tr = (tid / 16) * 8;
    int tc = (tid % 16) * 4;
    float acc[8][4];
    #pragma unroll
    for (int r = 0; r < 8; r++)
        #pragma unroll
        for (int c = 0; c < 4; c++) acc[r][c] = 0.f;

    for (int kc = 0; kc < IND; kc += 32) {
        for (int l = tid; l < 128 * 8; l += 256) {
            int r = l / 8, c4 = (l % 8) * 4;
            int gr = n0 + r;
            float4 v = (gr < NN) ? *(const float4*)(x + (size_t)gr * IND + kc + c4)
                                 : make_float4(0.f, 0.f, 0.f, 0.f);
            sx[r][c4] = v.x; sx[r][c4 + 1] = v.y; sx[r][c4 + 2] = v.z; sx[r][c4 + 3] = v.w;
        }
        for (int l = tid; l < 64 * 8; l += 256) {
            int r = l / 8, c4 = (l % 8) * 4;
            float4 v = *(const float4*)(Gmat_d + r * IND + kc + c4);
            sg[r][c4] = v.x; sg[r][c4 + 1] = v.y; sg[r][c4 + 2] = v.z; sg[r][c4 + 3] = v.w;
        }
        __syncthreads();
        #pragma unroll 8
        for (int k = 0; k < 32; k++) {
            float gv[4];
            #pragma unroll
            for (int c = 0; c < 4; c++) gv[c] = sg[tc + c][k];
            #pragma unroll
            for (int r = 0; r < 8; r++) {
                float xv = sx[tr + r][k];
                #pragma unroll
                for (int c = 0; c < 4; c++) acc[r][c] += xv * gv[c];
            }
        }
        __syncthreads();
    }
    #pragma unroll
    for (int r = 0; r < 8; r++) {
        int gr = n0 + tr + r;
        if (gr < NN) {
            *(float4*)(g_buf + (size_t)gr * HD + tc) =
                make_float4(acc[r][0], acc[r][1], acc[r][2], acc[r][3]);
            __half2* hp = (__half2*)(g_half + (size_t)gr * HD + tc);
            hp[0] = __floats2half2_rn(acc[r][0], acc[r][1]);
            hp[1] = __floats2half2_rn(acc[r][2], acc[r][3]);
        }
    }
}

// ---------------- k23: 16 edges/warp, coalesced att quarters + split-column ea ----------------
// Group of 4 lanes per edge-pair; lane j owns heads {2j,2j+1}. Lane j loads only att
// quarter j (coalesced 512B/instr across the warp), computes partial ea for all 8 heads
// over its 4 columns, then a 2-round select+shfl reduce lands each lane its 2 heads.
__global__ __launch_bounds__(256) void k23(const float* __restrict__ edge_attr) {
    __shared__ float sM2[EDIM * 9 + 8];   // sM2[c*9 + h]; stride 9 -> j-lanes hit distinct banks
    __shared__ float sz[8][HH];
    int tid = threadIdx.x;
    if (tid < EDIM * HH) {
        int c = tid / HH, h = tid % HH;
        sM2[c * 9 + h] = Mmat_d[h * EDIM + c];
    }
    __syncthreads();

    int lane = tid & 31, wid = tid >> 5;
    int j = lane & 3, g = lane >> 2;
    int h0 = 2 * j, h1 = 2 * j + 1;
    int e0 = blockIdx.x * K23_EPB + wid * 16 + g;
    int e1 = e0 + 8;

    // front-batched loads
    int2 sd0 = __ldcs(idx2_buf + e0);
    int2 sd1 = __ldcs(idx2_buf + e1);
    float4 aq0 = __ldcs((const float4*)(edge_attr + (size_t)e0 * EDIM) + j);  // quarter j, coalesced
    float4 aq1 = __ldcs((const float4*)(edge_attr + (size_t)e1 * EDIM) + j);

    const uint4* gs0 = (const uint4*)(g_half + (size_t)sd0.x * HD);
    const uint4* gd0 = (const uint4*)(g_half + (size_t)sd0.y * HD);
    const uint4* gs1 = (const uint4*)(g_half + (size_t)sd1.x * HD);
    const uint4* gd1 = (const uint4*)(g_half + (size_t)sd1.y * HD);
    uint4 ua00 = gs0[h0], ua01 = gs0[h1], ub00 = gd0[h0], ub01 = gd0[h1];
    uint4 ua10 = gs1[h0], ua11 = gs1[h1], ub10 = gd1[h0], ub11 = gd1[h1];

    // partial ea over this lane's 4 att columns, for heads 0-3 (Lo) and 4-7 (Hi)
    const float* mrow = sM2 + 4 * j * 9;
    float eL0[4], eH0[4], eL1[4], eH1[4];
    #pragma unroll
    for (int h = 0; h < 4; h++) {
        eL0[h] = aq0.x * mrow[h]     + aq0.y * mrow[9 + h]  + aq0.z * mrow[18 + h] + aq0.w * mrow[27 + h];
        eH0[h] = aq0.x * mrow[4 + h] + aq0.y * mrow[13 + h] + aq0.z * mrow[22 + h] + aq0.w * mrow[31 + h];
        eL1[h] = aq1.x * mrow[h]     + aq1.y * mrow[9 + h]  + aq1.z * mrow[18 + h] + aq1.w * mrow[27 + h];
        eH1[h] = aq1.x * mrow[4 + h] + aq1.y * mrow[13 + h] + aq1.z * mrow[22 + h] + aq1.w * mrow[31 + h];
    }
    // round 1 (xor 2): lanes j<2 collect heads 0-3, lanes j>=2 collect heads 4-7
    bool hi = (j & 2) != 0;
    float r0[4], r1[4];
    #pragma unroll
    for (int h = 0; h < 4; h++) {
        float mine0 = hi ? eH0[h] : eL0[h];
        float send0 = hi ? eL0[h] : eH0[h];
        r0[h] = mine0 + __shfl_xor_sync(0xffffffffu, send0, 2);
        float mine1 = hi ? eH1[h] : eL1[h];
        float send1 = hi ? eL1[h] : eH1[h];
        r1[h] = mine1 + __shfl_xor_sync(0xffffffffu, send1, 2);
    }
    // round 2 (xor 1): split the 4-head range; lane ends with heads {2j, 2j+1}
    bool odd = (j & 1) != 0;
    float m00 = odd ? r0[2] : r0[0], s00v = odd ? r0[0] : r0[2];
    float m01 = odd ? r0[3] : r0[1], s01v = odd ? r0[1] : r0[3];
    float m10 = odd ? r1[2] : r1[0], s10v = odd ? r1[0] : r1[2];
    float m11 = odd ? r1[3] : r1[1], s11v = odd ? r1[1] : r1[3];
    float ea00 = m00 + __shfl_xor_sync(0xffffffffu, s00v, 1);
    float ea01 = m01 + __shfl_xor_sync(0xffffffffu, s01v, 1);
    float ea10 = m10 + __shfl_xor_sync(0xffffffffu, s10v, 1);
    float ea11 = m11 + __shfl_xor_sync(0xffffffffu, s11v, 1);

    float d00 = hdot8(ua00, ub00);
    float d01 = hdot8(ua01, ub01);
    float d10 = hdot8(ua10, ub10);
    float d11 = hdot8(ua11, ub11);

    float s00 = d00 + 8.f * ea00; s00 = (s00 > 0.f) ? s00 : 0.2f * s00;
    float s01 = d01 + 8.f * ea01; s01 = (s01 > 0.f) ? s01 : 0.2f * s01;
    float s10 = d10 + 8.f * ea10; s10 = (s10 > 0.f) ? s10 : 0.2f * s10;
    float s11 = d11 + 8.f * ea11; s11 = (s11 > 0.f) ? s11 : 0.2f * s11;
    float p00 = __expf(s00 - EXP_OFS), p01 = __expf(s01 - EXP_OFS);
    float p10 = __expf(s10 - EXP_OFS), p11 = __expf(s11 - EXP_OFS);

    // scatter: pair lanes (j, j^1) -> one v4 red per pair per edge
    float q00 = __shfl_xor_sync(0xffffffffu, p00, 1);
    float q01 = __shfl_xor_sync(0xffffffffu, p01, 1);
    float q10 = __shfl_xor_sync(0xffffffffu, p10, 1);
    float q11 = __shfl_xor_sync(0xffffffffu, p11, 1);
    if ((j & 1) == 0) {
        float* sp0 = S_buf + (size_t)sd0.y * 8 + j * 2;
        asm volatile("red.global.add.v4.f32 [%0], {%1,%2,%3,%4};"
                     :: "l"(sp0), "f"(p00), "f"(p01), "f"(q00), "f"(q01) : "memory");
        float* sp1 = S_buf + (size_t)sd1.y * 8 + j * 2;
        asm volatile("red.global.add.v4.f32 [%0], {%1,%2,%3,%4};"
                     :: "l"(sp1), "f"(p10), "f"(p11), "f"(q10), "f"(q11) : "memory");
    }

    // Z partials: per-head sums over the warp's 16 edges
    float z0 = p00 + p10;
    float z1 = p01 + p11;
    #pragma unroll
    for (int o = 4; o <= 16; o <<= 1) {
        z0 += __shfl_xor_sync(0xffffffffu, z0, o);
        z1 += __shfl_xor_sync(0xffffffffu, z1, o);
    }
    if (lane < 4) {
        sz[wid][2 * lane]     = z0;
        sz[wid][2 * lane + 1] = z1;
    }
    __syncthreads();
    if (tid < 8) {
        float s = 0.f;
        #pragma unroll
        for (int w = 0; w < 8; w++) s += sz[w][tid];
        atomicAdd(&Zpad[tid * 32], s);
    }
}

// ---------------- k4: 2 nodes per lane-group epilogue ----------------
__global__ __launch_bounds__(256) void k4(const float* __restrict__ W_out, float* __restrict__ out) {
    __shared__ float sw[8 * 68];       // sw[h*68 + k*8 + d]
    __shared__ float sinvZ[8];
    int tid = threadIdx.x;
    for (int i = tid; i < 512; i += 256) {
        int k = i / 64, r = i % 64;
        int h = r / 8, d = r % 8;
        sw[h * 68 + k * 8 + d] = W_out[i];
    }
    if (tid < 8) sinvZ[tid] = 1.0f / Zpad[tid * 32];
    __syncthreads();

    int lane = tid & 31, wid = tid >> 5;
    int j = lane & 3;
    int h0 = 2 * j, h1 = 2 * j + 1;
    int n0 = blockIdx.x * 128 + wid * 16 + (lane >> 2);
    int n1 = n0 + 8;
    int c0 = (n0 < NN) ? n0 : (NN - 1);
    int c1 = (n1 < NN) ? n1 : (NN - 1);

    // front-batch all loads for both nodes
    const float4* gp0 = (const float4*)(g_buf + (size_t)c0 * HD) + 4 * j;
    const float4* gp1 = (const float4*)(g_buf + (size_t)c1 * HD) + 4 * j;
    float4 A0 = gp0[0], A1 = gp0[1], A2 = gp0[2], A3 = gp0[3];
    float4 B0 = gp1[0], B1 = gp1[1], B2 = gp1[2], B3 = gp1[3];
    float2 Sa = *(const float2*)(S_buf + (size_t)c0 * 8 + 2 * j);
    float2 Sb = *(const float2*)(S_buf + (size_t)c1 * 8 + 2 * j);

    float sa0 = Sa.x * sinvZ[h0], sa1 = Sa.y * sinvZ[h1];
    float sb0 = Sb.x * sinvZ[h0], sb1 = Sb.y * sinvZ[h1];

    float ga[8] = { A0.x*sa0, A0.y*sa0, A0.z*sa0, A0.w*sa0, A1.x*sa0, A1.y*sa0, A1.z*sa0, A1.w*sa0 };
    float gb[8] = { A2.x*sa1, A2.y*sa1, A2.z*sa1, A2.w*sa1, A3.x*sa1, A3.y*sa1, A3.z*sa1, A3.w*sa1 };
    float gc[8] = { B0.x*sb0, B0.y*sb0, B0.z*sb0, B0.w*sb0, B1.x*sb0, B1.y*sb0, B1.z*sb0, B1.w*sb0 };
    float gd[8] = { B2.x*sb1, B2.y*sb1, B2.z*sb1, B2.w*sb1, B3.x*sb1, B3.y*sb1, B3.z*sb1, B3.w*sb1 };

    float accA[8], accB[8];
    #pragma unroll
    for (int k = 0; k < 8; k++) {
        const float* w0 = sw + h0 * 68 + k * 8;
        const float* w1 = sw + h1 * 68 + k * 8;
        float sA = 0.f, sB = 0.f;
        #pragma unroll
        for (int d = 0; d < 8; d++) {
            sA += ga[d] * w0[d] + gb[d] * w1[d];
            sB += gc[d] * w0[d] + gd[d] * w1[d];
        }
        accA[k] = sA; accB[k] = sB;
    }
    #pragma unroll
    for (int o = 1; o <= 2; o <<= 1)
        #pragma unroll
        for (int k = 0; k < 8; k++) {
            accA[k] += __shfl_xor_sync(0xffffffffu, accA[k], o);
            accB[k] += __shfl_xor_sync(0xffffffffu, accB[k], o);
        }

    if (n0 < NN) {
        float2 r;
        r.x = fmaxf(accA[2 * j], 0.f);
        r.y = fmaxf(accA[2 * j + 1], 0.f);
        *(float2*)(out + (size_t)n0 * 8 + 2 * j) = r;
    }
    if (n1 < NN) {
        float2 r;
        r.x = fmaxf(accB[2 * j], 0.f);
        r.y = fmaxf(accB[2 * j + 1], 0.f);
        *(float2*)(out + (size_t)n1 * 8 + 2 * j) = r;
    }
}

// ---------------- launch ----------------
extern "C" void kernel_launch(void* const* d_in, const int* in_sizes, int n_in,
                              void* d_out, int out_size) {
    const float* x          = (const float*)d_in[0];
    const float* edge_attr  = (const float*)d_in[1];
    const float* W          = (const float*)d_in[2];
    const float* W_edge     = (const float*)d_in[3];
    const float* W_edge_att = (const float*)d_in[4];
    const float* W_att      = (const float*)d_in[5];
    const float* W_out      = (const float*)d_in[6];
    const void*  ei         = d_in[7];
    float* out = (float*)d_out;
    (void)in_sizes; (void)n_in; (void)out_size;

    k_prep<<<PREP_GRID, 256>>>(ei, W, W_edge, W_edge_att, W_att);
    k1<<<(NN + 127) / 128, 256>>>(x);
    k23<<<K23_GRID, 256>>>(edge_attr);
    k4<<<(NN + 127) / 128, 256>>>(W_out, out);
}

// round 10
// speedup vs baseline: 1.7182x; 1.0204x over previous
#include <cuda_runtime.h>
#include <cuda_fp16.h>
#include <math.h>

#define NN 50000
#define EE 800000
#define IND 128
#define EDIM 16
#define HH 8
#define HD 64

#define K23_EPB 256                    // 8 warps x 32 edges (4 per lane-group)
#define K23_GRID (EE / K23_EPB)        // 3125
#define PREP_GRID 6250
#define EXP_OFS 30.0f

// ---------------- scratch (device globals: no allocation allowed) ----------------
__device__ __align__(16) float  g_buf[NN * HD];     // fp32 g, for k4 (12.8 MB)
__device__ __align__(16) __half g_half[NN * HD];    // fp16 g for k23 gathers; row = 128B = 1 line
__device__ __align__(16) float  S_buf[NN * HH];     // 1.6 MB
__device__ __align__(16) float  Gmat_d[HD * IND];
__device__ __align__(16) float  Mmat_d[HH * EDIM];
__device__ __align__(128) float Zpad[HH * 32];      // one head per 128B line
__device__ __align__(16) int2   idx2_buf[EE];       // packed (src,dst)

__device__ __forceinline__ float hdot8(uint4 ua, uint4 ub) {
    float2 a, b; float d = 0.f;
    a = __half22float2(*(__half2*)&ua.x); b = __half22float2(*(__half2*)&ub.x); d += a.x*b.x + a.y*b.y;
    a = __half22float2(*(__half2*)&ua.y); b = __half22float2(*(__half2*)&ub.y); d += a.x*b.x + a.y*b.y;
    a = __half22float2(*(__half2*)&ua.z); b = __half22float2(*(__half2*)&ub.z); d += a.x*b.x + a.y*b.y;
    a = __half22float2(*(__half2*)&ua.w); b = __half22float2(*(__half2*)&ub.w); d += a.x*b.x + a.y*b.y;
    return d;
}

// ---------------- fused prep: idx normalize+pack, zero S/Z, fold weights ----------------
__global__ __launch_bounds__(256) void k_prep(const void* __restrict__ p,
                                              const float* __restrict__ W,
                                              const float* __restrict__ W_edge,
                                              const float* __restrict__ W_edge_att,
                                              const float* __restrict__ W_att) {
    __shared__ int s64;
    int tid = threadIdx.x;
    int b = blockIdx.x;

    // int64-vs-int32 detection (jnp.int64 silently becomes int32 when x64 off):
    // true int64 (<2^31) => every odd 32-bit word is 0; 32 zero high words is conclusive.
    if (tid < 32) {
        unsigned int v = ((const unsigned int*)p)[2 * tid + 1];
        unsigned int ball = __ballot_sync(0xffffffffu, v == 0u);
        if (tid == 0) s64 = (ball == 0xffffffffu) ? 1 : 0;
    }
    __syncthreads();
    int is64 = s64;

    if (tid < 128) {
        int e = b * 128 + tid;
        int src, dst;
        if (is64) { src = (int)((const long long*)p)[e]; dst = (int)((const long long*)p)[EE + e]; }
        else      { src = ((const int*)p)[e];            dst = ((const int*)p)[EE + e]; }
        idx2_buf[e] = make_int2(src, dst);
    }

    if (tid < 16) {
        int zi = b * 64 + tid * 4;
        *(float4*)(S_buf + zi) = make_float4(0.f, 0.f, 0.f, 0.f);
    }

    if (b == 0) {
        if (tid < HH * 32) Zpad[tid] = 0.f;
        if (tid < HH * EDIM) {
            int h = tid / EDIM, c = tid % EDIM;
            float s = 0.f;
            #pragma unroll 8
            for (int j = 0; j < 64; j++) s += W_edge_att[h * 64 + j] * W_edge[j * EDIM + c];
            Mmat_d[tid] = s;
        }
        for (int idx = tid; idx < HD * IND; idx += 256) {
            int j = idx / IND, c = idx % IND;
            int h = j / 8, k = j % 8;
            float s = 0.f;
            #pragma unroll
            for (int d = 0; d < 8; d++) s += W_att[k * 8 + d] * W[(h * 8 + d) * IND + c];
            Gmat_d[idx] = s;
        }
    }
}

// ---------------- k1: g = x @ Gmat^T  ([N,128] -> [N,64]), dual fp32+fp16 output ----------------
__global__ __launch_bounds__(256) void k1(const float* __restrict__ x) {
    __shared__ float sx[128][33];
    __shared__ float sg[64][33];
    int tid = threadIdx.x;
    int n0 = blockIdx.x * 128;
    int tr = (tid / 16) * 8;
    int tc = (tid % 16) * 4;
    float acc[8][4];
    #pragma unroll
    for (int r = 0; r < 8; r++)
        #pragma unroll
        for (int c = 0; c < 4; c++) acc[r][c] = 0.f;

    for (int kc = 0; kc < IND; kc += 32) {
        for (int l = tid; l < 128 * 8; l += 256) {
            int r = l / 8, c4 = (l % 8) * 4;
            int gr = n0 + r;
            float4 v = (gr < NN) ? *(const float4*)(x + (size_t)gr * IND + kc + c4)
                                 : make_float4(0.f, 0.f, 0.f, 0.f);
            sx[r][c4] = v.x; sx[r][c4 + 1] = v.y; sx[r][c4 + 2] = v.z; sx[r][c4 + 3] = v.w;
        }
        for (int l = tid; l < 64 * 8; l += 256) {
            int r = l / 8, c4 = (l % 8) * 4;
            float4 v = *(const float4*)(Gmat_d + r * IND + kc + c4);
            sg[r][c4] = v.x; sg[r][c4 + 1] = v.y; sg[r][c4 + 2] = v.z; sg[r][c4 + 3] = v.w;
        }
        __syncthreads();
        #pragma unroll 8
        for (int k = 0; k < 32; k++) {
            float gv[4];
            #pragma unroll
            for (int c = 0; c < 4; c++) gv[c] = sg[tc + c][k];
            #pragma unroll
            for (int r = 0; r < 8; r++) {
                float xv = sx[tr + r][k];
                #pragma unroll
                for (int c = 0; c < 4; c++) acc[r][c] += xv * gv[c];
            }
        }
        __syncthreads();
    }
    #pragma unroll
    for (int r = 0; r < 8; r++) {
        int gr = n0 + tr + r;
        if (gr < NN) {
            *(float4*)(g_buf + (size_t)gr * HD + tc) =
                make_float4(acc[r][0], acc[r][1], acc[r][2], acc[r][3]);
            __half2* hp = (__half2*)(g_half + (size_t)gr * HD + tc);
            hp[0] = __floats2half2_rn(acc[r][0], acc[r][1]);
            hp[1] = __floats2half2_rn(acc[r][2], acc[r][3]);
        }
    }
}

// ---------------- k23: 32 edges/warp (4 per lane-group) ----------------
// Group of 4 lanes; lane j owns heads {2j,2j+1} of the group's 4 edges.
__global__ __launch_bounds__(256) void k23(const float* __restrict__ edge_attr) {
    __shared__ float sM2[EDIM * 9 + 8];   // sM2[c*9 + h]
    __shared__ float sz[8][HH];
    int tid = threadIdx.x;
    if (tid < EDIM * HH) {
        int c = tid / HH, h = tid % HH;
        sM2[c * 9 + h] = Mmat_d[h * EDIM + c];
    }
    __syncthreads();

    int lane = tid & 31, wid = tid >> 5;
    int j = lane & 3, g = lane >> 2;
    int h0 = 2 * j, h1 = 2 * j + 1;
    int eb = blockIdx.x * K23_EPB + wid * 32 + g;   // edges eb, eb+8, eb+16, eb+24

    // ---- front-batch ALL loads: idx, att quarters, then gathers ----
    int2 sd[4];
    #pragma unroll
    for (int i = 0; i < 4; i++) sd[i] = __ldcs(idx2_buf + eb + 8 * i);

    float4 aq[4];
    #pragma unroll
    for (int i = 0; i < 4; i++)
        aq[i] = __ldcs((const float4*)(edge_attr + (size_t)(eb + 8 * i) * EDIM) + j);

    uint4 ua0[4], ua1[4], ub0[4], ub1[4];
    #pragma unroll
    for (int i = 0; i < 4; i++) {
        const uint4* gs = (const uint4*)(g_half + (size_t)sd[i].x * HD);
        const uint4* gd = (const uint4*)(g_half + (size_t)sd[i].y * HD);
        ua0[i] = gs[h0]; ua1[i] = gs[h1];
        ub0[i] = gd[h0]; ub1[i] = gd[h1];
    }

    // ---- ea while gathers are in flight: split-column partials + 2-round shfl ----
    const float* mrow = sM2 + 4 * j * 9;
    bool hi = (j & 2) != 0;
    bool odd = (j & 1) != 0;
    float ea0[4], ea1[4];
    #pragma unroll
    for (int i = 0; i < 4; i++) {
        float eL[4], eH[4];
        #pragma unroll
        for (int h = 0; h < 4; h++) {
            eL[h] = aq[i].x * mrow[h]     + aq[i].y * mrow[9 + h]  + aq[i].z * mrow[18 + h] + aq[i].w * mrow[27 + h];
            eH[h] = aq[i].x * mrow[4 + h] + aq[i].y * mrow[13 + h] + aq[i].z * mrow[22 + h] + aq[i].w * mrow[31 + h];
        }
        float r[4];
        #pragma unroll
        for (int h = 0; h < 4; h++) {
            float mine = hi ? eH[h] : eL[h];
            float send = hi ? eL[h] : eH[h];
            r[h] = mine + __shfl_xor_sync(0xffffffffu, send, 2);
        }
        float m0 = odd ? r[2] : r[0], s0 = odd ? r[0] : r[2];
        float m1 = odd ? r[3] : r[1], s1 = odd ? r[1] : r[3];
        ea0[i] = m0 + __shfl_xor_sync(0xffffffffu, s0, 1);
        ea1[i] = m1 + __shfl_xor_sync(0xffffffffu, s1, 1);
    }

    // ---- dots, activation, exp ----
    float p0[4], p1[4];
    #pragma unroll
    for (int i = 0; i < 4; i++) {
        float s0 = hdot8(ua0[i], ub0[i]) + 8.f * ea0[i];
        float s1 = hdot8(ua1[i], ub1[i]) + 8.f * ea1[i];
        s0 = (s0 > 0.f) ? s0 : 0.2f * s0;
        s1 = (s1 > 0.f) ? s1 : 0.2f * s1;
        p0[i] = __expf(s0 - EXP_OFS);
        p1[i] = __expf(s1 - EXP_OFS);
    }

    // ---- scatter: pair lanes (j, j^1) -> one v4 red per pair per edge ----
    #pragma unroll
    for (int i = 0; i < 4; i++) {
        float q0 = __shfl_xor_sync(0xffffffffu, p0[i], 1);
        float q1 = __shfl_xor_sync(0xffffffffu, p1[i], 1);
        if ((j & 1) == 0) {
            float* sp = S_buf + (size_t)sd[i].y * 8 + j * 2;
            asm volatile("red.global.add.v4.f32 [%0], {%1,%2,%3,%4};"
                         :: "l"(sp), "f"(p0[i]), "f"(p1[i]), "f"(q0), "f"(q1) : "memory");
        }
    }

    // ---- Z partials over the warp's 32 edges ----
    float z0 = p0[0] + p0[1] + p0[2] + p0[3];
    float z1 = p1[0] + p1[1] + p1[2] + p1[3];
    #pragma unroll
    for (int o = 4; o <= 16; o <<= 1) {
        z0 += __shfl_xor_sync(0xffffffffu, z0, o);
        z1 += __shfl_xor_sync(0xffffffffu, z1, o);
    }
    if (lane < 4) {
        sz[wid][2 * lane]     = z0;
        sz[wid][2 * lane + 1] = z1;
    }
    __syncthreads();
    if (tid < 8) {
        float s = 0.f;
        #pragma unroll
        for (int w = 0; w < 8; w++) s += sz[w][tid];
        atomicAdd(&Zpad[tid * 32], s);
    }
}

// ---------------- k4: 1 node per lane-group, fine-grain 128-thread blocks ----------------
__global__ __launch_bounds__(128) void k4(const float* __restrict__ W_out, float* __restrict__ out) {
    __shared__ float sw[8 * 68];       // sw[h*68 + k*8 + d]
    __shared__ float sinvZ[8];
    int tid = threadIdx.x;
    for (int i = tid; i < 512; i += 128) {
        int k = i / 64, r = i % 64;
        int h = r / 8, d = r % 8;
        sw[h * 68 + k * 8 + d] = W_out[i];
    }
    if (tid < 8) sinvZ[tid] = 1.0f / Zpad[tid * 32];
    __syncthreads();

    int lane = tid & 31, wid = tid >> 5;
    int j = lane & 3;
    int n = blockIdx.x * 32 + wid * 8 + (lane >> 2);
    int nc = (n < NN) ? n : (NN - 1);
    int h0 = 2 * j, h1 = 2 * j + 1;

    const float4* gp = (const float4*)(g_buf + (size_t)nc * HD) + 4 * j;
    float4 G0 = gp[0], G1 = gp[1], G2 = gp[2], G3 = gp[3];
    float2 S2 = *(const float2*)(S_buf + (size_t)nc * 8 + 2 * j);
    float sv0 = S2.x * sinvZ[h0];
    float sv1 = S2.y * sinvZ[h1];

    float ga[8] = { G0.x*sv0, G0.y*sv0, G0.z*sv0, G0.w*sv0, G1.x*sv0, G1.y*sv0, G1.z*sv0, G1.w*sv0 };
    float gb[8] = { G2.x*sv1, G2.y*sv1, G2.z*sv1, G2.w*sv1, G3.x*sv1, G3.y*sv1, G3.z*sv1, G3.w*sv1 };

    float acc[8];
    #pragma unroll
    for (int k = 0; k < 8; k++) {
        const float* w0 = sw + h0 * 68 + k * 8;
        const float* w1 = sw + h1 * 68 + k * 8;
        float s = 0.f;
        #pragma unroll
        for (int d = 0; d < 8; d++) s += ga[d] * w0[d] + gb[d] * w1[d];
        acc[k] = s;
    }
    #pragma unroll
    for (int o = 1; o <= 2; o <<= 1)
        #pragma unroll
        for (int k = 0; k < 8; k++) acc[k] += __shfl_xor_sync(0xffffffffu, acc[k], o);

    if (n < NN) {
        float2 r;
        r.x = fmaxf(acc[2 * j], 0.f);
        r.y = fmaxf(acc[2 * j + 1], 0.f);
        *(float2*)(out + (size_t)n * 8 + 2 * j) = r;
    }
}

// ---------------- launch ----------------
extern "C" void kernel_launch(void* const* d_in, const int* in_sizes, int n_in,
                              void* d_out, int out_size) {
    const float* x          = (const float*)d_in[0];
    const float* edge_attr  = (const float*)d_in[1];
    const float* W          = (const float*)d_in[2];
    const float* W_edge     = (const float*)d_in[3];
    const float* W_edge_att = (const float*)d_in[4];
    const float* W_att      = (const float*)d_in[5];
    const float* W_out      = (const float*)d_in[6];
    const void*  ei         = d_in[7];
    float* out = (float*)d_out;
    (void)in_sizes; (void)n_in; (void)out_size;

    k_prep<<<PREP_GRID, 256>>>(ei, W, W_edge, W_edge_att, W_att);
    k1<<<(NN + 127) / 128, 256>>>(x);
    k23<<<K23_GRID, 256>>>(edge_attr);
    k4<<<(NN + 31) / 32, 128>>>(W_out, out);
}